// round 15
// baseline (speedup 1.0000x reference)
#include <cuda_runtime.h>
#include <cstdint>

// dense_image_warp: out[b,y,x,c] = bilinear(image[b], y - flow[b,y,x,0], x - flow[b,y,x,1])
// B=8, H=512, W=512, C=16, fp32.
//
// Quad-per-pixel gather with shuffle exchange:
//  - 4 lanes per pixel; lane q holds 32B quarter of the 128B TL|TR span via one
//    LDG.256, and of the BL|BR span via a second LDG.256. Gather instructions
//    touch exactly the unique cache lines (wavefront floor).
//  - TR/BR quarters are brought to lanes 0,1 with shfl_xor(.,2) (shuffle pipe,
//    not l1tex). Lanes 0,1 compute all interpolation for their 8 channels and
//    store 32B each (STG.256, contiguous per warp).
// Block = 256 threads; 16x16 pixel tile; 4 iterations. Flow staged in smem.

#define Hh 512
#define Ww 512

#define LDG256(r, p)                                                        \
    asm volatile("ld.global.nc.v8.f32 {%0,%1,%2,%3,%4,%5,%6,%7}, [%8];"      \
        : "=f"(r[0]), "=f"(r[1]), "=f"(r[2]), "=f"(r[3]),                    \
          "=f"(r[4]), "=f"(r[5]), "=f"(r[6]), "=f"(r[7])                     \
        : "l"(p))

#define STG256(p, r)                                                        \
    asm volatile("st.global.v8.f32 [%0], {%1,%2,%3,%4,%5,%6,%7,%8};"         \
        :: "l"(p),                                                           \
           "f"(r[0]), "f"(r[1]), "f"(r[2]), "f"(r[3]),                       \
           "f"(r[4]), "f"(r[5]), "f"(r[6]), "f"(r[7]) : "memory")

__global__ __launch_bounds__(256) void warp_kernel_shfl(
    const float* __restrict__ img,     // [B,H,W,C]
    const float2* __restrict__ flow2,  // [B,H,W,2]
    float* __restrict__ out)
{
    __shared__ float2 sflow[256];      // 16x16 flow tile

    int t  = threadIdx.x;
    int q  = t & 3;                    // lane within quad
    int s  = t >> 2;                   // pixel slot within pass: 0..63
    int lx = s & 15;
    int ly = s >> 4;                   // 0..3

    int x0 = blockIdx.x * 16;
    int y0 = blockIdx.y * 16;
    int b  = blockIdx.z;
    int x  = x0 + lx;

    // ---- stage 16x16 flow tile ----
    {
        int fxp = x0 + (t & 15);
        int fyp = y0 + (t >> 4);
        int fp  = (((b << 9) + fyp) << 9) + fxp;
        sflow[t] = __ldcs(&flow2[fp]);
    }
    __syncthreads();

    #pragma unroll
    for (int it = 0; it < 4; it++) {
        int ty = it * 4 + ly;          // tile row 0..15
        int y  = y0 + ty;

        float2 f = sflow[(ty << 4) + lx];
        float qy = (float)y - f.x;
        float qx = (float)x - f.y;

        float fy = fminf(fmaxf(floorf(qy), 0.0f), (float)(Hh - 2));
        float fx = fminf(fmaxf(floorf(qx), 0.0f), (float)(Ww - 2));
        float ay = fminf(fmaxf(qy - fy, 0.0f), 1.0f);
        float ax = fminf(fmaxf(qx - fx, 0.0f), 1.0f);
        int iy = (int)fy;
        int ix = (int)fx;

        // lane q reads its 32B quarter of the 128B TL|TR span (and BL|BR)
        const char* base = (const char*)img
            + ((size_t)((((b << 9) + iy) << 9) + ix) << 6) + (q << 5);

        float t8[8], b8[8];
        LDG256(t8, base);
        LDG256(b8, base + (Ww << 6));

        // bring partner quarters: lanes 0,1 hold TL/BL, lanes 2,3 hold TR/BR
        float r8[8];
        #pragma unroll
        for (int i = 0; i < 8; i++) {
            float xt = __shfl_xor_sync(0xFFFFFFFFu, t8[i], 2);
            float xb = __shfl_xor_sync(0xFFFFFFFFu, b8[i], 2);
            // valid on lanes q<2: t8=TL, xt=TR, b8=BL, xb=BR
            float top = fmaf(ax, xt - t8[i], t8[i]);
            float bot = fmaf(ax, xb - b8[i], b8[i]);
            r8[i] = fmaf(ay, bot - top, top);
        }

        if (q < 2) {
            char* g = (char*)out
                + ((size_t)((((b << 9) + y) << 9) + x) << 6) + (q << 5);
            STG256(g, r8);
        }
    }
}

extern "C" void kernel_launch(void* const* d_in, const int* in_sizes, int n_in,
                              void* d_out, int out_size)
{
    const float*  img   = (const float*)d_in[0];
    const float2* flow2 = (const float2*)d_in[1];
    float* out = (float*)d_out;

    dim3 grid(Ww / 16, Hh / 16, 8);
    warp_kernel_shfl<<<grid, 256>>>(img, flow2, out);
}

// round 16
// speedup vs baseline: 1.0630x; 1.0630x over previous
#include <cuda_runtime.h>
#include <cstdint>

// dense_image_warp: out[b,y,x,c] = bilinear(image[b], y - flow[b,y,x,0], x - flow[b,y,x,1])
// B=8, H=512, W=512, C=16, fp32.
// Best-known structure (per-cg float4 gathers, smem flow, evict-last image
// loads, evict-first stores) with a taller 16(w) x 32(h) tile: 8 iterations
// per block amortize fixed costs and deepen vertical L1 reuse of gather rows.

#define Hh 512
#define Ww 512

__device__ __forceinline__ float4 ldg_el(const float4* p, uint64_t pol) {
    float4 v;
    asm volatile("ld.global.nc.L2::cache_hint.v4.f32 {%0,%1,%2,%3}, [%4], %5;"
                 : "=f"(v.x), "=f"(v.y), "=f"(v.z), "=f"(v.w)
                 : "l"(p), "l"(pol));
    return v;
}

__global__ __launch_bounds__(256) void warp_kernel_tall(
    const float4* __restrict__ img4,   // image as float4 (4 channels per group)
    const float2* __restrict__ flow2,  // flow as float2 per pixel
    float4* __restrict__ out4)
{
    __shared__ float2 sflow[512];      // 16x32 flow tile

    uint64_t pol;
    asm volatile("createpolicy.fractional.L2::evict_last.b64 %0, 1.0;" : "=l"(pol));

    int t  = threadIdx.x;
    int cg = t & 3;
    int lx = (t >> 2) & 15;
    int ly = t >> 6;                   // 0..3

    int x0 = blockIdx.x * 16;
    int y0 = blockIdx.y * 32;
    int b  = blockIdx.z;
    int x  = x0 + lx;

    // ---- stage 16x32 flow tile (2 rows per thread) ----
    {
        int fxp = x0 + (t & 15);
        int r0  = t >> 4;              // 0..15
        int fp0 = (((b << 9) + (y0 + r0)) << 9) + fxp;
        int fp1 = (((b << 9) + (y0 + r0 + 16)) << 9) + fxp;
        sflow[(r0 << 4) + (t & 15)]        = __ldcs(&flow2[fp0]);
        sflow[((r0 + 16) << 4) + (t & 15)] = __ldcs(&flow2[fp1]);
    }
    __syncthreads();

    #pragma unroll
    for (int it = 0; it < 8; it++) {
        int ty = it * 4 + ly;          // row within tile: 0..31
        int y  = y0 + ty;

        float2 f = sflow[(ty << 4) + lx];
        float qy = (float)y - f.x;
        float qx = (float)x - f.y;

        float fy = fminf(fmaxf(floorf(qy), 0.0f), (float)(Hh - 2));
        float fx = fminf(fmaxf(floorf(qx), 0.0f), (float)(Ww - 2));
        float ay = fminf(fmaxf(qy - fy, 0.0f), 1.0f);
        float ax = fminf(fmaxf(qx - fx, 0.0f), 1.0f);
        int iy = (int)fy;
        int ix = (int)fx;

        int base = (((b << 9) + iy) << 9) + ix;   // TL pixel index
        int a_tl = (base << 2) + cg;
        int a_bl = a_tl + (Ww << 2);

        float4 tl = ldg_el(&img4[a_tl], pol);
        float4 tr = ldg_el(&img4[a_tl + 4], pol);
        float4 bl = ldg_el(&img4[a_bl], pol);
        float4 br = ldg_el(&img4[a_bl + 4], pol);

        float4 top, bot, r;
        top.x = fmaf(ax, tr.x - tl.x, tl.x);
        top.y = fmaf(ax, tr.y - tl.y, tl.y);
        top.z = fmaf(ax, tr.z - tl.z, tl.z);
        top.w = fmaf(ax, tr.w - tl.w, tl.w);
        bot.x = fmaf(ax, br.x - bl.x, bl.x);
        bot.y = fmaf(ax, br.y - bl.y, bl.y);
        bot.z = fmaf(ax, br.z - bl.z, bl.z);
        bot.w = fmaf(ax, br.w - bl.w, bl.w);
        r.x = fmaf(ay, bot.x - top.x, top.x);
        r.y = fmaf(ay, bot.y - top.y, top.y);
        r.z = fmaf(ay, bot.z - top.z, top.z);
        r.w = fmaf(ay, bot.w - top.w, top.w);

        int p = (((b << 9) + y) << 9) + x;
        __stcs(&out4[(p << 2) + cg], r);
    }
}

extern "C" void kernel_launch(void* const* d_in, const int* in_sizes, int n_in,
                              void* d_out, int out_size)
{
    const float4* img4  = (const float4*)d_in[0];
    const float2* flow2 = (const float2*)d_in[1];
    float4* out4 = (float4*)d_out;

    dim3 grid(Ww / 16, Hh / 32, 8);
    warp_kernel_tall<<<grid, 256>>>(img4, flow2, out4);
}

// round 17
// speedup vs baseline: 1.0817x; 1.0176x over previous
#include <cuda_runtime.h>
#include <cstdint>

// dense_image_warp: out[b,y,x,c] = bilinear(image[b], y - flow[b,y,x,0], x - flow[b,y,x,1])
// B=8, H=512, W=512, C=16, fp32.
// Tall 16(w) x 32(h) tile (deep vertical L1 reuse, amortized fixed costs) +
// forced 32-reg budget (__launch_bounds__(256,8), unroll capped at 4) for
// 8 blocks/SM occupancy. Evict-last image gathers, evict-first stores,
// smem-staged flow.

#define Hh 512
#define Ww 512

__device__ __forceinline__ float4 ldg_el(const float4* p, uint64_t pol) {
    float4 v;
    asm volatile("ld.global.nc.L2::cache_hint.v4.f32 {%0,%1,%2,%3}, [%4], %5;"
                 : "=f"(v.x), "=f"(v.y), "=f"(v.z), "=f"(v.w)
                 : "l"(p), "l"(pol));
    return v;
}

__global__ __launch_bounds__(256, 8) void warp_kernel_tall8(
    const float4* __restrict__ img4,   // image as float4 (4 channels per group)
    const float2* __restrict__ flow2,  // flow as float2 per pixel
    float4* __restrict__ out4)
{
    __shared__ float2 sflow[512];      // 16x32 flow tile

    uint64_t pol;
    asm volatile("createpolicy.fractional.L2::evict_last.b64 %0, 1.0;" : "=l"(pol));

    int t  = threadIdx.x;
    int cg = t & 3;
    int lx = (t >> 2) & 15;
    int ly = t >> 6;                   // 0..3

    int x0 = blockIdx.x * 16;
    int y0 = blockIdx.y * 32;
    int b  = blockIdx.z;
    int x  = x0 + lx;

    // ---- stage 16x32 flow tile (2 rows per thread) ----
    {
        int fxp = x0 + (t & 15);
        int r0  = t >> 4;              // 0..15
        int fp0 = (((b << 9) + (y0 + r0)) << 9) + fxp;
        int fp1 = (((b << 9) + (y0 + r0 + 16)) << 9) + fxp;
        sflow[(r0 << 4) + (t & 15)]        = __ldcs(&flow2[fp0]);
        sflow[((r0 + 16) << 4) + (t & 15)] = __ldcs(&flow2[fp1]);
    }
    __syncthreads();

    #pragma unroll 4
    for (int it = 0; it < 8; it++) {
        int ty = it * 4 + ly;          // row within tile: 0..31
        int y  = y0 + ty;

        float2 f = sflow[(ty << 4) + lx];
        float qy = (float)y - f.x;
        float qx = (float)x - f.y;

        float fy = fminf(fmaxf(floorf(qy), 0.0f), (float)(Hh - 2));
        float fx = fminf(fmaxf(floorf(qx), 0.0f), (float)(Ww - 2));
        float ay = fminf(fmaxf(qy - fy, 0.0f), 1.0f);
        float ax = fminf(fmaxf(qx - fx, 0.0f), 1.0f);
        int iy = (int)fy;
        int ix = (int)fx;

        int base = (((b << 9) + iy) << 9) + ix;   // TL pixel index
        int a_tl = (base << 2) + cg;
        int a_bl = a_tl + (Ww << 2);

        float4 tl = ldg_el(&img4[a_tl], pol);
        float4 tr = ldg_el(&img4[a_tl + 4], pol);
        float4 bl = ldg_el(&img4[a_bl], pol);
        float4 br = ldg_el(&img4[a_bl + 4], pol);

        float4 top, bot, r;
        top.x = fmaf(ax, tr.x - tl.x, tl.x);
        top.y = fmaf(ax, tr.y - tl.y, tl.y);
        top.z = fmaf(ax, tr.z - tl.z, tl.z);
        top.w = fmaf(ax, tr.w - tl.w, tl.w);
        bot.x = fmaf(ax, br.x - bl.x, bl.x);
        bot.y = fmaf(ax, br.y - bl.y, bl.y);
        bot.z = fmaf(ax, br.z - bl.z, bl.z);
        bot.w = fmaf(ax, br.w - bl.w, bl.w);
        r.x = fmaf(ay, bot.x - top.x, top.x);
        r.y = fmaf(ay, bot.y - top.y, top.y);
        r.z = fmaf(ay, bot.z - top.z, top.z);
        r.w = fmaf(ay, bot.w - top.w, top.w);

        int p = (((b << 9) + y) << 9) + x;
        __stcs(&out4[(p << 2) + cg], r);
    }
}

extern "C" void kernel_launch(void* const* d_in, const int* in_sizes, int n_in,
                              void* d_out, int out_size)
{
    const float4* img4  = (const float4*)d_in[0];
    const float2* flow2 = (const float2*)d_in[1];
    float4* out4 = (float4*)d_out;

    dim3 grid(Ww / 16, Hh / 32, 8);
    warp_kernel_tall8<<<grid, 256>>>(img4, flow2, out4);
}